// round 4
// baseline (speedup 1.0000x reference)
#include <cuda_runtime.h>

// Problem constants
#define BB 4
#define LL 512
#define VV 4
#define DD 256
#define DS 16
#define DI 512
#define DCONV 4
#define DTR 16

static constexpr int M_ROWS = BB * LL;          // 2048 rows per view
static constexpr size_t OUT_ONE = (size_t)BB * LL * VV * DD;  // 2,097,152

// -------- scratch (static device globals; no allocation allowed) ----------
__device__ __align__(16) float g_xn  [(size_t)VV * M_ROWS * DD];       //  8 MB
__device__ __align__(16) float g_xz  [(size_t)VV * M_ROWS * 2 * DI];   // 32 MB (xi | z)
__device__ __align__(16) float g_xc  [(size_t)VV * M_ROWS * DI];       // 16 MB
__device__ __align__(16) float g_xdbl[(size_t)VV * M_ROWS * 48];       // 1.5 MB (dt|B|C)
__device__ __align__(16) float g_y   [(size_t)VV * M_ROWS * DI];       // 16 MB

// -------- packed f32x2 helpers --------------------------------------------
__device__ __forceinline__ unsigned long long pk2(float x, float y) {
    unsigned long long r;
    asm("mov.b64 %0, {%1, %2};" : "=l"(r) : "f"(x), "f"(y));
    return r;
}
__device__ __forceinline__ unsigned long long ffma2(unsigned long long a,
                                                    unsigned long long b,
                                                    unsigned long long c) {
    unsigned long long d;
    asm("fma.rn.f32x2 %0, %1, %2, %3;" : "=l"(d) : "l"(a), "l"(b), "l"(c));
    return d;
}
__device__ __forceinline__ float2 upk2(unsigned long long v) {
    float2 r;
    asm("mov.b64 {%0, %1}, %2;" : "=f"(r.x), "=f"(r.y) : "l"(v));
    return r;
}
__device__ __forceinline__ float silu_f(float x) {
    return x / (1.0f + __expf(-x));
}

// ============================================================================
// Kernel 1: LayerNorm  x(B,L,V,D) -> g_xn (V, B*L, D)
// ============================================================================
__global__ __launch_bounds__(256)
void ln_kernel(const float* __restrict__ x,
               const float* __restrict__ gamma,
               const float* __restrict__ beta)
{
    const int row = blockIdx.x;        // b*L + l  (0..2047)
    const int v   = blockIdx.y;
    const int d   = threadIdx.x;       // 0..255

    float val = x[((size_t)row * VV + v) * DD + d];

    float s = val, q = val * val;
    #pragma unroll
    for (int o = 16; o; o >>= 1) {
        s += __shfl_xor_sync(0xffffffffu, s, o);
        q += __shfl_xor_sync(0xffffffffu, q, o);
    }
    __shared__ float sh[16];
    const int w = d >> 5, ln = d & 31;
    if (ln == 0) { sh[w] = s; sh[w + 8] = q; }
    __syncthreads();
    if (d == 0) {
        float S = 0.f, Q = 0.f;
        #pragma unroll
        for (int i = 0; i < 8; i++) { S += sh[i]; Q += sh[i + 8]; }
        const float mu  = S * (1.0f / DD);
        const float var = Q * (1.0f / DD) - mu * mu;
        sh[0] = mu;
        sh[1] = rsqrtf(var + 1e-5f);
    }
    __syncthreads();
    const float mu = sh[0], rs = sh[1];
    g_xn[((size_t)v * M_ROWS + row) * DD + d] =
        (val - mu) * rs * gamma[v * DD + d] + beta[v * DD + d];
}

// ============================================================================
// Kernel 2/4/6: batched NT GEMM  C[v] = A[v](MxK) * W[v](NxK)^T, fp32 via f32x2
//   MODE 0: g_xn  @ w_in^T  -> g_xz    (M=2048, N=1024, K=256)
//   MODE 1: g_xc  @ w_x^T   -> g_xdbl  (M=2048, N=48,   K=512)
//   MODE 2: g_y   @ w_out^T -> d_out   (M=2048, N=256,  K=512) scattered+dup
// ============================================================================
template<int MODE>
__global__ __launch_bounds__(256)
void gemm_nt(const float* __restrict__ Wg, float* __restrict__ Cout, size_t dupOfs)
{
    constexpr int N = (MODE == 0) ? 1024 : (MODE == 1 ? 48 : 256);
    constexpr int K = (MODE == 0) ? 256 : 512;

    const int v = blockIdx.z;
    const float* A = (MODE == 0 ? g_xn : (MODE == 1 ? g_xc : g_y))
                     + (size_t)v * M_ROWS * K;
    const float* W = Wg + (size_t)v * N * K;

    const int m0 = blockIdx.y * 128;
    const int n0 = blockIdx.x * 64;

    __shared__ __align__(16) float As[16][128];   // [k][m]
    __shared__ __align__(16) float Ws[16][64];    // [k][n]

    const int tid = threadIdx.x;
    const int tm = tid >> 4;     // 0..15 -> rows tm*8..tm*8+7
    const int tn = tid & 15;     // 0..15 -> cols tn*4..tn*4+3

    unsigned long long acc[8][2];
    #pragma unroll
    for (int i = 0; i < 8; i++) { acc[i][0] = 0ull; acc[i][1] = 0ull; }

    const int lrow = tid >> 2;   // loader row
    const int lkq  = tid & 3;    // loader k-quad

    for (int kk = 0; kk < K; kk += 16) {
        // --- load A tile 128x16 (transposed into smem) ---
        #pragma unroll
        for (int p = 0; p < 2; p++) {
            const int row = lrow + p * 64;
            float4 val = *reinterpret_cast<const float4*>(
                A + (size_t)(m0 + row) * K + kk + lkq * 4);
            As[lkq * 4 + 0][row] = val.x;
            As[lkq * 4 + 1][row] = val.y;
            As[lkq * 4 + 2][row] = val.z;
            As[lkq * 4 + 3][row] = val.w;
        }
        // --- load W tile 64x16 ---
        {
            float4 val = make_float4(0.f, 0.f, 0.f, 0.f);
            if (MODE != 1 || (n0 + lrow) < N)
                val = *reinterpret_cast<const float4*>(
                    W + (size_t)(n0 + lrow) * K + kk + lkq * 4);
            Ws[lkq * 4 + 0][lrow] = val.x;
            Ws[lkq * 4 + 1][lrow] = val.y;
            Ws[lkq * 4 + 2][lrow] = val.z;
            Ws[lkq * 4 + 3][lrow] = val.w;
        }
        __syncthreads();

        #pragma unroll
        for (int k = 0; k < 16; k++) {
            const float4 a0 = *reinterpret_cast<const float4*>(&As[k][tm * 8]);
            const float4 a1 = *reinterpret_cast<const float4*>(&As[k][tm * 8 + 4]);
            const ulonglong2 w = *reinterpret_cast<const ulonglong2*>(&Ws[k][tn * 4]);
            const float a[8] = {a0.x, a0.y, a0.z, a0.w, a1.x, a1.y, a1.z, a1.w};
            #pragma unroll
            for (int i = 0; i < 8; i++) {
                const unsigned long long ai = pk2(a[i], a[i]);
                acc[i][0] = ffma2(ai, w.x, acc[i][0]);
                acc[i][1] = ffma2(ai, w.y, acc[i][1]);
            }
        }
        __syncthreads();
    }

    // --- epilogue ---
    float* Cbuf = (MODE == 0) ? g_xz : (MODE == 1 ? g_xdbl : Cout);
    #pragma unroll
    for (int i = 0; i < 8; i++) {
        const int row = m0 + tm * 8 + i;
        #pragma unroll
        for (int p = 0; p < 2; p++) {
            const int col = n0 + tn * 4 + p * 2;
            const float2 r = upk2(acc[i][p]);
            if (MODE == 2) {
                // out layout (B,L,V,D): ((b*L+l)*V + v)*D + col, duplicated tuple
                const size_t o = ((size_t)row * VV + v) * DD + col;
                *reinterpret_cast<float2*>(Cbuf + o) = r;
                *reinterpret_cast<float2*>(Cbuf + dupOfs + o) = r;
            } else {
                if (MODE != 1 || col < N)
                    *reinterpret_cast<float2*>(
                        Cbuf + ((size_t)v * M_ROWS + row) * N + col) = r;
            }
        }
    }
}

// ============================================================================
// Kernel 3: depthwise causal conv (k=4) + bias + silu :  g_xz[:, :DI] -> g_xc
// ============================================================================
__global__ __launch_bounds__(256)
void conv_silu_kernel(const float* __restrict__ cw, const float* __restrict__ cb)
{
    const int idx = blockIdx.x * 256 + threadIdx.x;   // VV*BB*LL*(DI/4) = 1,048,576
    const int d4 = idx & 127;                          // DI/4 = 128
    const int l  = (idx >> 7) & (LL - 1);
    const int bv = idx >> 16;                          // v*BB + b
    const int v  = bv >> 2;

    const float* cwp = cw + ((size_t)v * DI + d4 * 4) * DCONV;
    const float4 c0 = *reinterpret_cast<const float4*>(cwp);
    const float4 c1 = *reinterpret_cast<const float4*>(cwp + 4);
    const float4 c2 = *reinterpret_cast<const float4*>(cwp + 8);
    const float4 c3 = *reinterpret_cast<const float4*>(cwp + 12);
    const float cwa0[4] = {c0.x, c0.y, c0.z, c0.w};
    const float cwa1[4] = {c1.x, c1.y, c1.z, c1.w};
    const float cwa2[4] = {c2.x, c2.y, c2.z, c2.w};
    const float cwa3[4] = {c3.x, c3.y, c3.z, c3.w};

    float4 acc = *reinterpret_cast<const float4*>(cb + (size_t)v * DI + d4 * 4);

    const float* xiBase = g_xz + (size_t)bv * LL * (2 * DI) + d4 * 4;
    #pragma unroll
    for (int k = 0; k < DCONV; k++) {
        const int lp = l - (DCONV - 1) + k;
        if (lp >= 0) {
            const float4 xi = *reinterpret_cast<const float4*>(
                xiBase + (size_t)lp * (2 * DI));
            acc.x = fmaf(cwa0[k], xi.x, acc.x);
            acc.y = fmaf(cwa1[k], xi.y, acc.y);
            acc.z = fmaf(cwa2[k], xi.z, acc.z);
            acc.w = fmaf(cwa3[k], xi.w, acc.w);
        }
    }
    acc.x = silu_f(acc.x);
    acc.y = silu_f(acc.y);
    acc.z = silu_f(acc.z);
    acc.w = silu_f(acc.w);
    *reinterpret_cast<float4*>(
        g_xc + ((size_t)bv * LL + l) * DI + d4 * 4) = acc;
}

// ============================================================================
// Kernel 5: fused selective scan
//   per (v,b,d): delta = softplus(dt_lo . w_dt[d] + b_dt[d])  (butterfly reduce)
//                h[n]  = exp(delta*A[d,n])*h[n] + delta*B[n]*xc
//                y     = (sum_n h[n]*C[n] + xc*D_skip[d]) * silu(z)
//   8-lane groups, each lane owns 2 of the 16 states.
// ============================================================================
__global__ __launch_bounds__(256)
void scan_kernel(const float* __restrict__ w_dt, const float* __restrict__ b_dt,
                 const float* __restrict__ A_log, const float* __restrict__ D_skip)
{
    const int gid = blockIdx.x * 32 + (threadIdx.x >> 3);   // 0..8191 = v*B*DI
    const int j   = threadIdx.x & 7;                         // lane in group
    const int d   = gid & (DI - 1);
    const int b   = (gid >> 9) & (BB - 1);
    const int v   = gid >> 11;
    const int n0  = j * 2;

    const float* wdtp = w_dt + ((size_t)v * DI + d) * DTR + n0;
    const float wdt0 = wdtp[0], wdt1 = wdtp[1];
    const float* alp = A_log + ((size_t)v * DI + d) * DS + n0;
    const float negA0 = -__expf(alp[0]);
    const float negA1 = -__expf(alp[1]);
    const float bdt = b_dt[(size_t)v * DI + d];
    const float dsk = D_skip[(size_t)v * DI + d];

    const int bv = v * BB + b;
    const float* xdb = g_xdbl + (size_t)bv * LL * 48;
    const float* xcP = g_xc + (size_t)bv * LL * DI + d;
    const float* zP  = g_xz + (size_t)bv * LL * (2 * DI) + DI + d;
    float*       yP  = g_y  + (size_t)bv * LL * DI + d;

    float h0 = 0.f, h1 = 0.f;

    #pragma unroll 2
    for (int l = 0; l < LL; l++) {
        const float* rp = xdb + l * 48;
        const float2 dt = *reinterpret_cast<const float2*>(rp + n0);
        const float2 Bc = *reinterpret_cast<const float2*>(rp + 16 + n0);
        const float2 Cc = *reinterpret_cast<const float2*>(rp + 32 + n0);
        const float xc = __ldg(xcP + (size_t)l * DI);

        // delta = softplus(dt_lo . w_dt + b_dt), reduced over 16 (8 lanes x 2)
        float p = fmaf(dt.x, wdt0, dt.y * wdt1);
        p += __shfl_xor_sync(0xffffffffu, p, 4);
        p += __shfl_xor_sync(0xffffffffu, p, 2);
        p += __shfl_xor_sync(0xffffffffu, p, 1);
        const float pre = p + bdt;
        const float delta = fmaxf(pre, 0.f) + log1pf(__expf(-fabsf(pre)));

        const float dxc = delta * xc;
        h0 = fmaf(__expf(delta * negA0), h0, dxc * Bc.x);
        h1 = fmaf(__expf(delta * negA1), h1, dxc * Bc.y);

        float t = fmaf(h1, Cc.y, h0 * Cc.x);
        t += __shfl_xor_sync(0xffffffffu, t, 4);
        t += __shfl_xor_sync(0xffffffffu, t, 2);
        t += __shfl_xor_sync(0xffffffffu, t, 1);

        if (j == 0) {
            const float z = zP[(size_t)l * (2 * DI)];
            yP[(size_t)l * DI] = fmaf(xc, dsk, t) * silu_f(z);
        }
    }
}

// ============================================================================
// launch
// ============================================================================
extern "C" void kernel_launch(void* const* d_in, const int* in_sizes, int n_in,
                              void* d_out, int out_size)
{
    const float* x      = (const float*)d_in[0];
    const float* ln_g   = (const float*)d_in[1];
    const float* ln_b   = (const float*)d_in[2];
    const float* w_in   = (const float*)d_in[3];
    const float* conv_w = (const float*)d_in[4];
    const float* conv_b = (const float*)d_in[5];
    const float* w_x    = (const float*)d_in[6];
    const float* w_dt   = (const float*)d_in[7];
    const float* b_dt   = (const float*)d_in[8];
    const float* A_log  = (const float*)d_in[9];
    const float* D_skip = (const float*)d_in[10];
    const float* w_out  = (const float*)d_in[11];
    float* out = (float*)d_out;

    // tuple (agents, agents): duplicate second half only if the harness
    // allocated room for it.
    const size_t dup = ((size_t)out_size >= 2 * OUT_ONE) ? OUT_ONE : 0;

    // 1) layernorm per (view,row)
    ln_kernel<<<dim3(M_ROWS, VV), 256>>>(x, ln_g, ln_b);

    // 2) xz = xn @ w_in^T   (M=2048, N=1024, K=256) per view
    gemm_nt<0><<<dim3(1024 / 64, M_ROWS / 128, VV), 256>>>(w_in, nullptr, 0);

    // 3) depthwise causal conv + silu -> xc
    conv_silu_kernel<<<(VV * BB * LL * (DI / 4)) / 256, 256>>>(conv_w, conv_b);

    // 4) xdbl = xc @ w_x^T  (N=48, K=512)
    gemm_nt<1><<<dim3(1, M_ROWS / 128, VV), 256>>>(w_x, nullptr, 0);

    // 5) fused delta + selective scan + gating -> y
    scan_kernel<<<(VV * BB * DI) / 32, 256>>>(w_dt, b_dt, A_log, D_skip);

    // 6) out = y @ w_out^T scattered into (B,L,V,D), duplicated
    gemm_nt<2><<<dim3(256 / 64, M_ROWS / 128, VV), 256>>>(w_out, out, dup);
}